// round 11
// baseline (speedup 1.0000x reference)
#include <cuda_runtime.h>
#include <math.h>

// ---------------- problem constants ----------------
#define NROWS 50000
#define MPAD  50048
#define NFEAT 300
#define LWORDS 16
#define EDGES 800000
#define HID 64
#define JOINT 128
#define BATCH 4096
#define ALPHA 0.2f
#define EPSV 1e-16f

// ---------------- scratch ----------------
__device__ float g_Pw[(size_t)NROWS * HID];
__device__ float g_h1[2][(size_t)NROWS * HID];
__device__ float g_out1[2][(size_t)MPAD * HID];
__device__ float g_h2[2][(size_t)MPAD * JOINT];
__device__ float g_X[2][(size_t)MPAD * JOINT];
__device__ float g_f[2][MPAD];
__device__ float g_g[2][MPAD];
__device__ int   g_cnt[2][NROWS];
__device__ int   g_incl[2][NROWS];
__device__ int   g_rowptr[2][NROWS + 1];
__device__ int   g_tmp[2][NROWS];
__device__ int   g_cols[2][EDGES];
__device__ int   g_bsums[2][64];
__device__ int   g_bpre[2][64];
__device__ float g_att[2];

// ---------------- f32x2 helpers ----------------
__device__ __forceinline__ unsigned long long pack_dup(float a) {
    unsigned long long r;
    asm("mov.b64 %0,{%1,%1};" : "=l"(r) : "f"(a));
    return r;
}
__device__ __forceinline__ void fma_x2(unsigned long long& acc, unsigned long long a,
                                       unsigned long long b) {
    asm("fma.rn.f32x2 %0,%1,%2,%3;" : "=l"(acc) : "l"(a), "l"(b), "l"(acc));
}
__device__ __forceinline__ void unpack2(unsigned long long v, float& lo, float& hi) {
    asm("mov.b64 {%0,%1},%2;" : "=f"(lo), "=f"(hi) : "l"(v));
}
__device__ __forceinline__ float tanh_fast(float x) {
    float r;
    asm("tanh.approx.f32 %0,%1;" : "=f"(r) : "f"(x));
    return r;
}

// ---------------- small utility kernels ----------------
__global__ void zero_att_k(float* att) {
    if (threadIdx.x < 2) att[threadIdx.x] = 0.0f;
}

__global__ void zero_int_k(int* p, int n) {
    int i = blockIdx.x * blockDim.x + threadIdx.x;
    if (i < n) p[i] = 0;
}

// ---------------- GEMM (single view per launch) ----------------
// k-major As, double-buffered smem, register prefetch.
// f32x2 packed FMA, pairs along N: B fragments load packed directly, A scalars duplicated.
// MODE 0: store C (+ f/g epilogue if FUSE).  MODE 1: sum(tanh(C)*proj) -> atomicAdd(red).
template <int BM, int BN, int BK, int TM, int TN, int MODE, bool FUSE>
__global__ void __launch_bounds__((BM / TM) * (BN / TN))
gemm_k(const float* __restrict__ A, const float* __restrict__ Bm,
       float* __restrict__ C, int M, int K,
       const float* __restrict__ av, float* __restrict__ fo, float* __restrict__ go,
       const float* __restrict__ proj, float* __restrict__ red) {
    constexpr int TX = BN / TN;
    constexpr int TY = BM / TM;
    constexpr int NT = TX * TY;
    constexpr int KV = BK / 4;
    constexpr int NV = BN / 4;
    constexpr int AV4 = (BM * BK) / (4 * NT);
    constexpr int BV4 = (BK * BN) / (4 * NT);
    static_assert(AV4 * 4 * NT == BM * BK, "A tile divisible");
    static_assert(BV4 * 4 * NT == BK * BN, "B tile divisible");
    static_assert(TM % 4 == 0 && TN % 4 == 0, "frag vec");

    __shared__ __align__(16) float As[2][BK][BM + 4];
    __shared__ __align__(16) float Bs[2][BK][BN];

    int tid = threadIdx.x;
    int tx = tid % TX;
    int ty = tid / TX;
    int m0 = blockIdx.x * BM;
    int nk = (K + BK - 1) / BK;

    // packed accumulators along N: acc2[i][j] holds cols (2j, 2j+1) for local row i
    unsigned long long acc2[TM][TN / 2];
#pragma unroll
    for (int i = 0; i < TM; i++)
#pragma unroll
        for (int j = 0; j < TN / 2; j++) acc2[i][j] = 0ULL;

    float4 pa[AV4], pb[BV4];

    auto fetch = [&](int kb) {
        int k0 = kb * BK;
#pragma unroll
        for (int u = 0; u < AV4; u++) {
            int t = tid + u * NT;
            int m = t / KV, kq = t % KV;
            int gm = m0 + m, gk = k0 + kq * 4;
            float4 v = make_float4(0.f, 0.f, 0.f, 0.f);
            if (gm < M) {
                if (gk + 3 < K) {
                    v = *reinterpret_cast<const float4*>(&A[(size_t)gm * K + gk]);
                } else {
                    if (gk + 0 < K) v.x = A[(size_t)gm * K + gk + 0];
                    if (gk + 1 < K) v.y = A[(size_t)gm * K + gk + 1];
                    if (gk + 2 < K) v.z = A[(size_t)gm * K + gk + 2];
                    if (gk + 3 < K) v.w = A[(size_t)gm * K + gk + 3];
                }
            }
            pa[u] = v;
        }
#pragma unroll
        for (int u = 0; u < BV4; u++) {
            int t = tid + u * NT;
            int k = t / NV, nq = t % NV;
            int gk = k0 + k;
            float4 v = make_float4(0.f, 0.f, 0.f, 0.f);
            if (gk < K) v = *reinterpret_cast<const float4*>(&Bm[(size_t)gk * BN + nq * 4]);
            pb[u] = v;
        }
    };
    auto stage = [&](int buf) {
#pragma unroll
        for (int u = 0; u < AV4; u++) {
            int t = tid + u * NT;
            int m = t / KV, kq = t % KV;
            As[buf][kq * 4 + 0][m] = pa[u].x;
            As[buf][kq * 4 + 1][m] = pa[u].y;
            As[buf][kq * 4 + 2][m] = pa[u].z;
            As[buf][kq * 4 + 3][m] = pa[u].w;
        }
#pragma unroll
        for (int u = 0; u < BV4; u++) {
            int t = tid + u * NT;
            int k = t / NV, nq = t % NV;
            *reinterpret_cast<float4*>(&Bs[buf][k][nq * 4]) = pb[u];
        }
    };

    fetch(0);
    stage(0);
    __syncthreads();

    int buf = 0;
    for (int kb = 0; kb < nk; kb++) {
        if (kb + 1 < nk) fetch(kb + 1);
#pragma unroll
        for (int k = 0; k < BK; k++) {
            // A fragment: TM m-contiguous floats -> float4 loads, dup each scalar
            unsigned long long ad[TM];
#pragma unroll
            for (int i = 0; i < TM; i += 4) {
                float4 a4 = *reinterpret_cast<const float4*>(&As[buf][k][ty * TM + i]);
                ad[i + 0] = pack_dup(a4.x);
                ad[i + 1] = pack_dup(a4.y);
                ad[i + 2] = pack_dup(a4.z);
                ad[i + 3] = pack_dup(a4.w);
            }
            // B fragment: TN n-contiguous floats -> packed pairs load directly
            unsigned long long b2[TN / 2];
#pragma unroll
            for (int j = 0; j < TN; j += 4) {
                ulonglong2 u = *reinterpret_cast<const ulonglong2*>(&Bs[buf][k][tx * TN + j]);
                b2[j / 2] = u.x;
                b2[j / 2 + 1] = u.y;
            }
#pragma unroll
            for (int i = 0; i < TM; i++)
#pragma unroll
                for (int j = 0; j < TN / 2; j++) fma_x2(acc2[i][j], ad[i], b2[j]);
        }
        if (kb + 1 < nk) stage(buf ^ 1);
        __syncthreads();
        buf ^= 1;
    }

    // unpack (N-contiguous, matches store order)
    float val[TM][TN];
#pragma unroll
    for (int i = 0; i < TM; i++)
#pragma unroll
        for (int j = 0; j < TN / 2; j++) unpack2(acc2[i][j], val[i][2 * j], val[i][2 * j + 1]);

    if (MODE == 0) {
#pragma unroll
        for (int i = 0; i < TM; i++) {
            int m = m0 + ty * TM + i;
            if (m < M) {
#pragma unroll
                for (int j = 0; j < TN; j += 4) {
                    float4 v4 = make_float4(val[i][j], val[i][j + 1], val[i][j + 2], val[i][j + 3]);
                    *reinterpret_cast<float4*>(&C[(size_t)m * BN + tx * TN + j]) = v4;
                }
            }
        }
        if (FUSE) {
#pragma unroll
            for (int i = 0; i < TM; i++) {
                float sf = 0.0f, sg = 0.0f;
#pragma unroll
                for (int j = 0; j < TN; j++) {
                    int c = tx * TN + j;
                    sf = fmaf(val[i][j], av[c], sf);
                    sg = fmaf(val[i][j], av[BN + c], sg);
                }
#pragma unroll
                for (int o = TX / 2; o; o >>= 1) {
                    sf += __shfl_xor_sync(0xffffffffu, sf, o);
                    sg += __shfl_xor_sync(0xffffffffu, sg, o);
                }
                int m = m0 + ty * TM + i;
                if (tx == 0 && m < M) { fo[m] = sf; go[m] = sg; }
            }
        }
    } else {
        // OOB rows are zero-filled -> tanh(0)=0 contributes nothing
        float s = 0.0f;
#pragma unroll
        for (int j = 0; j < TN; j++) {
            float pj = proj[tx * TN + j];
#pragma unroll
            for (int i = 0; i < TM; i++) s = fmaf(tanh_fast(val[i][j]), pj, s);
        }
#pragma unroll
        for (int o = 16; o; o >>= 1) s += __shfl_xor_sync(0xffffffffu, s, o);
        __shared__ float wred[NT / 32];
        if ((tid & 31) == 0) wred[tid >> 5] = s;
        __syncthreads();
        if (tid == 0) {
            float tot = 0.0f;
            for (int w = 0; w < NT / 32; w++) tot += wred[w];
            atomicAdd(red, tot);
        }
    }
}

// ---------------- gather-mean + fused f/g (tweet layer 1) ----------------
__global__ void gather_mean_fg_k(const int* __restrict__ idx, const float* __restrict__ P,
                                 float* __restrict__ out, const float* __restrict__ a,
                                 float* __restrict__ f, float* __restrict__ g) {
    int row = (blockIdx.x * blockDim.x + threadIdx.x) >> 5;
    int lane = threadIdx.x & 31;
    if (row >= NROWS) return;
    int w = idx[row * LWORDS + (lane & 15)];
    float acc0 = 0.0f, acc1 = 0.0f;
#pragma unroll
    for (int l = 0; l < LWORDS; l++) {
        int wl = __shfl_sync(0xffffffffu, w, l);
        acc0 += P[(size_t)wl * HID + lane];
        acc1 += P[(size_t)wl * HID + 32 + lane];
    }
    float h0 = acc0 * (1.0f / LWORDS);
    float h1 = acc1 * (1.0f / LWORDS);
    out[(size_t)row * HID + lane] = h0;
    out[(size_t)row * HID + 32 + lane] = h1;
    float sf = h0 * a[lane] + h1 * a[32 + lane];
    float sg = h0 * a[64 + lane] + h1 * a[96 + lane];
#pragma unroll
    for (int o = 16; o; o >>= 1) {
        sf += __shfl_xor_sync(0xffffffffu, sf, o);
        sg += __shfl_xor_sync(0xffffffffu, sg, o);
    }
    if (lane == 0) { f[row] = sf; g[row] = sg; }
}

// ---------------- CSR build (both graphs per launch) ----------------
__global__ void count2_k(const int* __restrict__ r0, const int* __restrict__ r1,
                         int* __restrict__ cnt) {
    int e = blockIdx.x * blockDim.x + threadIdx.x;
    if (e < EDGES) atomicAdd(&cnt[r0[e]], 1);
    else if (e < 2 * EDGES) atomicAdd(&cnt[NROWS + r1[e - EDGES]], 1);
}

__global__ void scan_block2_k(const int* __restrict__ cnt, int* __restrict__ incl,
                              int* __restrict__ bsums) {
    __shared__ int sm[1024];
    int gb = blockIdx.y * NROWS;
    int i = blockIdx.x * 1024 + threadIdx.x;
    int v = (i < NROWS) ? cnt[gb + i] : 0;
    sm[threadIdx.x] = v;
    __syncthreads();
#pragma unroll
    for (int o = 1; o < 1024; o <<= 1) {
        int t = (threadIdx.x >= o) ? sm[threadIdx.x - o] : 0;
        __syncthreads();
        sm[threadIdx.x] += t;
        __syncthreads();
    }
    if (i < NROWS) incl[gb + i] = sm[threadIdx.x];
    if (threadIdx.x == 1023) bsums[blockIdx.y * 64 + blockIdx.x] = sm[1023];
}

__global__ void scan_sums2_k(const int* __restrict__ bsums, int* __restrict__ bpre, int nb) {
    __shared__ int wsum;
    int gb = blockIdx.x * 64;
    int lane = threadIdx.x;
    int orig = (lane < nb) ? bsums[gb + lane] : 0;
    int v = orig;
#pragma unroll
    for (int o = 1; o < 32; o <<= 1) {
        int t = __shfl_up_sync(0xffffffffu, v, o);
        if ((lane & 31) >= o) v += t;
    }
    if (lane == 31) wsum = v;
    __syncthreads();
    int incl = v + ((lane >= 32) ? wsum : 0);
    if (lane < nb) bpre[gb + lane] = incl - orig;
}

__global__ void finalize2_k(const int* __restrict__ incl, const int* __restrict__ cnt,
                            const int* __restrict__ bpre, int* __restrict__ rowptr,
                            int* __restrict__ tmp) {
    int gidx = blockIdx.y;
    int i = blockIdx.x * blockDim.x + threadIdx.x;
    if (i < NROWS) {
        int ex = incl[gidx * NROWS + i] - cnt[gidx * NROWS + i] + bpre[gidx * 64 + (i >> 10)];
        rowptr[gidx * (NROWS + 1) + i] = ex;
        tmp[gidx * NROWS + i] = ex;
    }
    if (i == 0) rowptr[gidx * (NROWS + 1) + NROWS] = EDGES;
}

__global__ void scatter2_k(const int* __restrict__ e0, const int* __restrict__ e1,
                           int* __restrict__ tmp, int* __restrict__ cols) {
    int e = blockIdx.x * blockDim.x + threadIdx.x;
    if (e < EDGES) {
        int r = e0[e];
        int p = atomicAdd(&tmp[r], 1);
        cols[p] = e0[e + EDGES];
    } else if (e < 2 * EDGES) {
        int ee = e - EDGES;
        int r = e1[ee];
        int p = atomicAdd(&tmp[NROWS + r], 1);
        cols[EDGES + p] = e1[ee + EDGES];
    }
}

// ---------------- SpGAT aggregation (single view per launch) ----------------
template <int D>
__global__ void agg_k(const int* __restrict__ rp, const int* __restrict__ cl,
                      const float* __restrict__ f, const float* __restrict__ gg,
                      const float* __restrict__ h, float* __restrict__ out) {
    int row = (blockIdx.x * blockDim.x + threadIdx.x) >> 5;
    int lane = threadIdx.x & 31;
    if (row >= NROWS) return;
    int s = rp[row];
    int e = rp[row + 1];
    float fr = f[row];
    constexpr int V = D / 32;
    float acc[V];
#pragma unroll
    for (int j = 0; j < V; j++) acc[j] = 0.0f;
    float den = 0.0f;
    for (int p = s; p < e; p++) {
        int c = cl[p];
        float x = fr + gg[c];
        float lr = x > 0.0f ? x : ALPHA * x;
        float w = __expf(-lr);
        den += w;
        const float* hc = h + (size_t)c * D;
#pragma unroll
        for (int j = 0; j < V; j++) acc[j] = fmaf(w, hc[lane + j * 32], acc[j]);
    }
    float inv = 1.0f / (den + EPSV);
#pragma unroll
    for (int j = 0; j < V; j++) {
        float v = acc[j] * inv;
        v = v > 0.0f ? v : __expf(v) - 1.0f;  // ELU
        out[(size_t)row * D + lane + j * 32] = v;
    }
}

// ---------------- final fusion + classifier + log_softmax ----------------
__global__ void final_k(const float* __restrict__ twX, const float* __restrict__ tuX,
                        const int* __restrict__ g0, const int* __restrict__ g1,
                        const float* __restrict__ outW, const float* __restrict__ outB,
                        const float* __restrict__ att, float* __restrict__ out) {
    int b = (blockIdx.x * blockDim.x + threadIdx.x) >> 5;
    int lane = threadIdx.x & 31;
    if (b >= BATCH) return;
    float a0 = att[0] * (1.0f / NROWS);
    float a1 = att[1] * (1.0f / NROWS);
    float mx = fmaxf(a0, a1);
    float e0 = expf(a0 - mx), e1 = expf(a1 - mx);
    float inv = 1.0f / (e0 + e1);
    float w0 = e0 * inv, w1 = e1 * inv;
    int i0 = g0[b], i1 = g1[b];
    float l0 = 0.0f, l1 = 0.0f;
#pragma unroll
    for (int j = 0; j < JOINT / 32; j++) {
        int c = lane + j * 32;
        float fv = w0 * twX[(size_t)i0 * JOINT + c] + w1 * tuX[(size_t)i1 * JOINT + c];
        l0 = fmaf(fv, outW[c], l0);
        l1 = fmaf(fv, outW[JOINT + c], l1);
    }
#pragma unroll
    for (int o = 16; o; o >>= 1) {
        l0 += __shfl_xor_sync(0xffffffffu, l0, o);
        l1 += __shfl_xor_sync(0xffffffffu, l1, o);
    }
    if (lane == 0) {
        l0 += outB[0];
        l1 += outB[1];
        float m = fmaxf(l0, l1);
        float lse = m + logf(expf(l0 - m) + expf(l1 - m));
        out[b * 2 + 0] = l0 - lse;
        out[b * 2 + 1] = l1 - lse;
    }
}

// ---------------- host launcher ----------------
extern "C" void kernel_launch(void* const* d_in, const int* in_sizes, int n_in,
                              void* d_out, int out_size) {
    const float *word_emb, *user_emb, *tw_W1, *tw_a1, *tw_W2, *tw_a2;
    const float *tu_W1, *tu_a1, *tu_W2, *tu_a2, *weight_W, *weight_proj, *out_W, *out_b;
    const int *feat_idx, *tw_edges, *ut_edges, *tw_gidx, *ut_gidx;

    if (in_sizes[0] == NROWS * NFEAT) {
        word_emb    = (const float*)d_in[0];
        user_emb    = (const float*)d_in[1];
        tw_W1       = (const float*)d_in[2];
        tw_a1       = (const float*)d_in[3];
        tw_W2       = (const float*)d_in[4];
        tw_a2       = (const float*)d_in[5];
        tu_W1       = (const float*)d_in[6];
        tu_a1       = (const float*)d_in[7];
        tu_W2       = (const float*)d_in[8];
        tu_a2       = (const float*)d_in[9];
        weight_W    = (const float*)d_in[10];
        weight_proj = (const float*)d_in[11];
        out_W       = (const float*)d_in[12];
        out_b       = (const float*)d_in[13];
        feat_idx    = (const int*)d_in[14];
        tw_edges    = (const int*)d_in[15];
        ut_edges    = (const int*)d_in[16];
        tw_gidx     = (const int*)d_in[17];
        ut_gidx     = (const int*)d_in[18];
    } else {
        feat_idx    = (const int*)d_in[0];
        tw_edges    = (const int*)d_in[1];
        ut_edges    = (const int*)d_in[2];
        tw_gidx     = (const int*)d_in[3];
        ut_gidx     = (const int*)d_in[4];
        word_emb    = (const float*)d_in[5];
        user_emb    = (const float*)d_in[6];
        tw_W1       = (const float*)d_in[7];
        tw_a1       = (const float*)d_in[8];
        tw_W2       = (const float*)d_in[9];
        tw_a2       = (const float*)d_in[10];
        tu_W1       = (const float*)d_in[11];
        tu_a1       = (const float*)d_in[12];
        tu_W2       = (const float*)d_in[13];
        tu_a2       = (const float*)d_in[14];
        weight_W    = (const float*)d_in[15];
        weight_proj = (const float*)d_in[16];
        out_W       = (const float*)d_in[17];
        out_b       = (const float*)d_in[18];
    }

    float *Pw, *h1, *out1, *h2, *X, *fb, *gb, *att;
    int *cnt, *incl, *rowptr, *tmp, *cols, *bsums, *bpre;
    cudaGetSymbolAddress((void**)&Pw, g_Pw);
    cudaGetSymbolAddress((void**)&h1, g_h1);
    cudaGetSymbolAddress((void**)&out1, g_out1);
    cudaGetSymbolAddress((void**)&h2, g_h2);
    cudaGetSymbolAddress((void**)&X, g_X);
    cudaGetSymbolAddress((void**)&fb, g_f);
    cudaGetSymbolAddress((void**)&gb, g_g);
    cudaGetSymbolAddress((void**)&att, g_att);
    cudaGetSymbolAddress((void**)&cnt, g_cnt);
    cudaGetSymbolAddress((void**)&incl, g_incl);
    cudaGetSymbolAddress((void**)&rowptr, g_rowptr);
    cudaGetSymbolAddress((void**)&tmp, g_tmp);
    cudaGetSymbolAddress((void**)&cols, g_cols);
    cudaGetSymbolAddress((void**)&bsums, g_bsums);
    cudaGetSymbolAddress((void**)&bpre, g_bpre);

    float* h1_tw  = h1;
    float* h1_u   = h1 + (size_t)NROWS * HID;
    float* out1_u = out1 + (size_t)MPAD * HID;
    float* h2_u   = h2 + (size_t)MPAD * JOINT;
    float* X_u    = X + (size_t)MPAD * JOINT;

    const int WG = (NROWS * 32 + 255) / 256;
    const int GB1 = (NROWS + 127) / 128;       // 391 (BM=128)
    const int GB2 = (NROWS + 63) / 64;         // 782 (BM=64)
    const int NB = (NROWS + 1023) / 1024;      // 49
    const int NG = (NROWS + 255) / 256;
    const int E2G = (2 * EDGES + 255) / 256;

    static cudaStream_t s1 = nullptr, s2 = nullptr;
    static cudaEvent_t evFork = nullptr, evCSR = nullptr, evV1 = nullptr;
    if (s1 == nullptr) {
        cudaStreamCreateWithFlags(&s1, cudaStreamNonBlocking);
        cudaStreamCreateWithFlags(&s2, cudaStreamNonBlocking);
        cudaEventCreateWithFlags(&evFork, cudaEventDisableTiming);
        cudaEventCreateWithFlags(&evCSR, cudaEventDisableTiming);
        cudaEventCreateWithFlags(&evV1, cudaEventDisableTiming);
    }

    // ---- fork ----
    zero_att_k<<<1, 32>>>(att);
    cudaEventRecord(evFork, 0);
    cudaStreamWaitEvent(s1, evFork, 0);
    cudaStreamWaitEvent(s2, evFork, 0);

    // s1: CSR front
    zero_int_k<<<(2 * NROWS + 255) / 256, 256, 0, s1>>>(cnt, 2 * NROWS);
    count2_k<<<E2G, 256, 0, s1>>>(tw_edges, ut_edges, cnt);

    // main: view0 GEMM1 -> Pw  (ncu slot 3)
    gemm_k<128, 64, 16, 4, 8, 0, false><<<GB1, 256>>>(
        word_emb, tw_W1, Pw, NROWS, NFEAT, nullptr, nullptr, nullptr, nullptr, nullptr);

    // s2: view1 GEMM1 -> h1_u (+ f/g layer1)
    gemm_k<128, 64, 16, 4, 8, 0, true><<<GB1, 256, 0, s2>>>(
        user_emb, tu_W1, h1_u, NROWS, NFEAT, tu_a1, fb + MPAD, gb + MPAD, nullptr, nullptr);

    // s1: rest of CSR
    scan_block2_k<<<dim3(NB, 2), 1024, 0, s1>>>(cnt, incl, bsums);
    scan_sums2_k<<<2, 64, 0, s1>>>(bsums, bpre, NB);
    finalize2_k<<<dim3(NG, 2), 256, 0, s1>>>(incl, cnt, bpre, rowptr, tmp);
    scatter2_k<<<E2G, 256, 0, s1>>>(tw_edges, ut_edges, tmp, cols);
    cudaEventRecord(evCSR, s1);

    // main: tweet h1 = gather-mean (+ f/g layer1 view0)
    gather_mean_fg_k<<<WG, 256>>>(feat_idx, Pw, h1_tw, tw_a1, fb, gb);

    // ---- view0 chain on main ----
    cudaStreamWaitEvent(0, evCSR, 0);
    agg_k<HID><<<WG, 256>>>(rowptr, cols, fb, gb, h1_tw, out1);
    gemm_k<64, 128, 16, 4, 8, 0, true><<<GB2, 256>>>(
        out1, tw_W2, h2, NROWS, HID, tw_a2, fb, gb, nullptr, nullptr);
    agg_k<JOINT><<<WG, 256>>>(rowptr, cols, fb, gb, h2, X);
    gemm_k<64, 128, 16, 4, 8, 1, false><<<GB2, 256>>>(
        X, weight_W, nullptr, NROWS, JOINT, nullptr, nullptr, nullptr, weight_proj, att + 0);

    // ---- view1 chain on s2 ----
    cudaStreamWaitEvent(s2, evCSR, 0);
    agg_k<HID><<<WG, 256, 0, s2>>>(rowptr + (NROWS + 1), cols + EDGES,
                                   fb + MPAD, gb + MPAD, h1_u, out1_u);
    gemm_k<64, 128, 16, 4, 8, 0, true><<<GB2, 256, 0, s2>>>(
        out1_u, tu_W2, h2_u, NROWS, HID, tu_a2, fb + MPAD, gb + MPAD, nullptr, nullptr);
    agg_k<JOINT><<<WG, 256, 0, s2>>>(rowptr + (NROWS + 1), cols + EDGES,
                                     fb + MPAD, gb + MPAD, h2_u, X_u);
    gemm_k<64, 128, 16, 4, 8, 1, false><<<GB2, 256, 0, s2>>>(
        X_u, weight_W, nullptr, NROWS, JOINT, nullptr, nullptr, nullptr, weight_proj, att + 1);
    cudaEventRecord(evV1, s2);

    // ---- join + final ----
    cudaStreamWaitEvent(0, evV1, 0);
    final_k<<<(BATCH * 32 + 255) / 256, 256>>>(X, X_u, tw_gidx, ut_gidx,
                                               out_W, out_b, att, (float*)d_out);
}

// round 13
// speedup vs baseline: 1.2551x; 1.2551x over previous
#include <cuda_runtime.h>
#include <math.h>

// ---------------- problem constants ----------------
#define NROWS 50000
#define MPAD  50048
#define NFEAT 300
#define LWORDS 16
#define EDGES 800000
#define HID 64
#define JOINT 128
#define BATCH 4096
#define ALPHA 0.2f
#define EPSV 1e-16f

// ---------------- scratch ----------------
__device__ float g_Pw[(size_t)NROWS * HID];
__device__ float g_h1[2][(size_t)NROWS * HID];
__device__ float g_out1[2][(size_t)MPAD * HID];
__device__ float g_h2[2][(size_t)MPAD * JOINT];
__device__ float g_X[2][(size_t)MPAD * JOINT];
__device__ float g_f[2][MPAD];
__device__ float g_g[2][MPAD];
__device__ int   g_cnt[2][NROWS];
__device__ int   g_incl[2][NROWS];
__device__ int   g_rowptr[2][NROWS + 1];
__device__ int   g_tmp[2][NROWS];
__device__ int   g_cols[2][EDGES];
__device__ int   g_bsums[2][64];
__device__ int   g_bpre[2][64];
__device__ float g_att[2];

// ---------------- f32x2 helpers ----------------
__device__ __forceinline__ unsigned long long pack_dup(float a) {
    unsigned long long r;
    asm("mov.b64 %0,{%1,%1};" : "=l"(r) : "f"(a));
    return r;
}
__device__ __forceinline__ void fma_x2(unsigned long long& acc, unsigned long long a,
                                       unsigned long long b) {
    asm("fma.rn.f32x2 %0,%1,%2,%3;" : "=l"(acc) : "l"(a), "l"(b), "l"(acc));
}
__device__ __forceinline__ void unpack2(unsigned long long v, float& lo, float& hi) {
    asm("mov.b64 {%0,%1},%2;" : "=f"(lo), "=f"(hi) : "l"(v));
}
__device__ __forceinline__ float tanh_fast(float x) {
    float r;
    asm("tanh.approx.f32 %0,%1;" : "=f"(r) : "f"(x));
    return r;
}

// ---------------- small utility kernels ----------------
__global__ void zero_att_k(float* att) {
    if (threadIdx.x < 2) att[threadIdx.x] = 0.0f;
}

__global__ void zero_int_k(int* p, int n) {
    int i = blockIdx.x * blockDim.x + threadIdx.x;
    if (i < n) p[i] = 0;
}

// ---------------- GEMM (single view per launch) ----------------
// k-major As, double-buffered smem, register prefetch of global tiles AND
// register double-buffered shared fragments (hides LDS latency within a warp).
// f32x2 packed FMA, pairs along M (A frags load packed directly).
// MODE 0: store C (+ f/g epilogue if FUSE).  MODE 1: sum(tanh(C)*proj) -> atomicAdd(red).
template <int BM, int BN, int BK, int TM, int TN, int MODE, bool FUSE>
__global__ void __launch_bounds__((BM / TM) * (BN / TN))
gemm_k(const float* __restrict__ A, const float* __restrict__ Bm,
       float* __restrict__ C, int M, int K,
       const float* __restrict__ av, float* __restrict__ fo, float* __restrict__ go,
       const float* __restrict__ proj, float* __restrict__ red) {
    constexpr int TX = BN / TN;
    constexpr int TY = BM / TM;
    constexpr int NT = TX * TY;
    constexpr int KV = BK / 4;
    constexpr int NV = BN / 4;
    constexpr int AV4 = (BM * BK) / (4 * NT);
    constexpr int BV4 = (BK * BN) / (4 * NT);
    static_assert(AV4 * 4 * NT == BM * BK, "A tile divisible");
    static_assert(BV4 * 4 * NT == BK * BN, "B tile divisible");
    static_assert(TM % 4 == 0 && TN % 4 == 0, "frag vec");

    __shared__ __align__(16) float As[2][BK][BM + 4];
    __shared__ __align__(16) float Bs[2][BK][BN];

    int tid = threadIdx.x;
    int tx = tid % TX;
    int ty = tid / TX;
    int m0 = blockIdx.x * BM;
    int nk = (K + BK - 1) / BK;

    // packed accumulators: pair (2*i, 2*i+1) of M rows, column j
    unsigned long long acc2[TM / 2][TN];
#pragma unroll
    for (int i = 0; i < TM / 2; i++)
#pragma unroll
        for (int j = 0; j < TN; j++) acc2[i][j] = 0ULL;

    float4 pa[AV4], pb[BV4];

    auto fetch = [&](int kb) {
        int k0 = kb * BK;
#pragma unroll
        for (int u = 0; u < AV4; u++) {
            int t = tid + u * NT;
            int m = t / KV, kq = t % KV;
            int gm = m0 + m, gk = k0 + kq * 4;
            float4 v = make_float4(0.f, 0.f, 0.f, 0.f);
            if (gm < M) {
                if (gk + 3 < K) {
                    v = *reinterpret_cast<const float4*>(&A[(size_t)gm * K + gk]);
                } else {
                    if (gk + 0 < K) v.x = A[(size_t)gm * K + gk + 0];
                    if (gk + 1 < K) v.y = A[(size_t)gm * K + gk + 1];
                    if (gk + 2 < K) v.z = A[(size_t)gm * K + gk + 2];
                    if (gk + 3 < K) v.w = A[(size_t)gm * K + gk + 3];
                }
            }
            pa[u] = v;
        }
#pragma unroll
        for (int u = 0; u < BV4; u++) {
            int t = tid + u * NT;
            int k = t / NV, nq = t % NV;
            int gk = k0 + k;
            float4 v = make_float4(0.f, 0.f, 0.f, 0.f);
            if (gk < K) v = *reinterpret_cast<const float4*>(&Bm[(size_t)gk * BN + nq * 4]);
            pb[u] = v;
        }
    };
    auto stage = [&](int buf) {
#pragma unroll
        for (int u = 0; u < AV4; u++) {
            int t = tid + u * NT;
            int m = t / KV, kq = t % KV;
            As[buf][kq * 4 + 0][m] = pa[u].x;
            As[buf][kq * 4 + 1][m] = pa[u].y;
            As[buf][kq * 4 + 2][m] = pa[u].z;
            As[buf][kq * 4 + 3][m] = pa[u].w;
        }
#pragma unroll
        for (int u = 0; u < BV4; u++) {
            int t = tid + u * NT;
            int k = t / NV, nq = t % NV;
            *reinterpret_cast<float4*>(&Bs[buf][k][nq * 4]) = pb[u];
        }
    };

    fetch(0);
    stage(0);
    __syncthreads();

    // register fragment double-buffers
    unsigned long long a2[2][TM / 2];
    float4 braw[2][TN / 4];

    int buf = 0;
    for (int kb = 0; kb < nk; kb++) {
        if (kb + 1 < nk) fetch(kb + 1);

        // prime fragment slot 0 with k=0
#pragma unroll
        for (int i = 0; i < TM; i += 4) {
            ulonglong2 u = *reinterpret_cast<const ulonglong2*>(&As[buf][0][ty * TM + i]);
            a2[0][i / 2] = u.x;
            a2[0][i / 2 + 1] = u.y;
        }
#pragma unroll
        for (int j = 0; j < TN; j += 4)
            braw[0][j / 4] = *reinterpret_cast<const float4*>(&Bs[buf][0][tx * TN + j]);

#pragma unroll
        for (int k = 0; k < BK; k++) {
            int cur = k & 1;
            int nxt = cur ^ 1;
            if (k + 1 < BK) {
#pragma unroll
                for (int i = 0; i < TM; i += 4) {
                    ulonglong2 u =
                        *reinterpret_cast<const ulonglong2*>(&As[buf][k + 1][ty * TM + i]);
                    a2[nxt][i / 2] = u.x;
                    a2[nxt][i / 2 + 1] = u.y;
                }
#pragma unroll
                for (int j = 0; j < TN; j += 4)
                    braw[nxt][j / 4] =
                        *reinterpret_cast<const float4*>(&Bs[buf][k + 1][tx * TN + j]);
            }
            // duplicate B scalars at use site (ALU pipe, overlaps FMA)
            unsigned long long bd[TN];
#pragma unroll
            for (int j = 0; j < TN; j += 4) {
                float4 b4 = braw[cur][j / 4];
                bd[j] = pack_dup(b4.x);
                bd[j + 1] = pack_dup(b4.y);
                bd[j + 2] = pack_dup(b4.z);
                bd[j + 3] = pack_dup(b4.w);
            }
#pragma unroll
            for (int i = 0; i < TM / 2; i++)
#pragma unroll
                for (int j = 0; j < TN; j++) fma_x2(acc2[i][j], a2[cur][i], bd[j]);
        }
        if (kb + 1 < nk) stage(buf ^ 1);
        __syncthreads();
        buf ^= 1;
    }

    float val[TM][TN];
#pragma unroll
    for (int i = 0; i < TM / 2; i++)
#pragma unroll
        for (int j = 0; j < TN; j++) unpack2(acc2[i][j], val[2 * i][j], val[2 * i + 1][j]);

    if (MODE == 0) {
#pragma unroll
        for (int i = 0; i < TM; i++) {
            int m = m0 + ty * TM + i;
            if (m < M) {
#pragma unroll
                for (int j = 0; j < TN; j += 4) {
                    float4 v4 = make_float4(val[i][j], val[i][j + 1], val[i][j + 2], val[i][j + 3]);
                    *reinterpret_cast<float4*>(&C[(size_t)m * BN + tx * TN + j]) = v4;
                }
            }
        }
        if (FUSE) {
#pragma unroll
            for (int i = 0; i < TM; i++) {
                float sf = 0.0f, sg = 0.0f;
#pragma unroll
                for (int j = 0; j < TN; j++) {
                    int c = tx * TN + j;
                    sf = fmaf(val[i][j], av[c], sf);
                    sg = fmaf(val[i][j], av[BN + c], sg);
                }
#pragma unroll
                for (int o = TX / 2; o; o >>= 1) {
                    sf += __shfl_xor_sync(0xffffffffu, sf, o);
                    sg += __shfl_xor_sync(0xffffffffu, sg, o);
                }
                int m = m0 + ty * TM + i;
                if (tx == 0 && m < M) { fo[m] = sf; go[m] = sg; }
            }
        }
    } else {
        // OOB rows are zero-filled -> tanh(0)=0 contributes nothing
        float s = 0.0f;
#pragma unroll
        for (int j = 0; j < TN; j++) {
            float pj = proj[tx * TN + j];
#pragma unroll
            for (int i = 0; i < TM; i++) s = fmaf(tanh_fast(val[i][j]), pj, s);
        }
#pragma unroll
        for (int o = 16; o; o >>= 1) s += __shfl_xor_sync(0xffffffffu, s, o);
        __shared__ float wred[NT / 32];
        if ((tid & 31) == 0) wred[tid >> 5] = s;
        __syncthreads();
        if (tid == 0) {
            float tot = 0.0f;
            for (int w = 0; w < NT / 32; w++) tot += wred[w];
            atomicAdd(red, tot);
        }
    }
}

// ---------------- gather-mean + fused f/g (tweet layer 1) ----------------
__global__ void gather_mean_fg_k(const int* __restrict__ idx, const float* __restrict__ P,
                                 float* __restrict__ out, const float* __restrict__ a,
                                 float* __restrict__ f, float* __restrict__ g) {
    int row = (blockIdx.x * blockDim.x + threadIdx.x) >> 5;
    int lane = threadIdx.x & 31;
    if (row >= NROWS) return;
    int w = idx[row * LWORDS + (lane & 15)];
    float acc0 = 0.0f, acc1 = 0.0f;
#pragma unroll
    for (int l = 0; l < LWORDS; l++) {
        int wl = __shfl_sync(0xffffffffu, w, l);
        acc0 += P[(size_t)wl * HID + lane];
        acc1 += P[(size_t)wl * HID + 32 + lane];
    }
    float h0 = acc0 * (1.0f / LWORDS);
    float h1 = acc1 * (1.0f / LWORDS);
    out[(size_t)row * HID + lane] = h0;
    out[(size_t)row * HID + 32 + lane] = h1;
    float sf = h0 * a[lane] + h1 * a[32 + lane];
    float sg = h0 * a[64 + lane] + h1 * a[96 + lane];
#pragma unroll
    for (int o = 16; o; o >>= 1) {
        sf += __shfl_xor_sync(0xffffffffu, sf, o);
        sg += __shfl_xor_sync(0xffffffffu, sg, o);
    }
    if (lane == 0) { f[row] = sf; g[row] = sg; }
}

// ---------------- CSR build (both graphs per launch) ----------------
__global__ void count2_k(const int* __restrict__ r0, const int* __restrict__ r1,
                         int* __restrict__ cnt) {
    int e = blockIdx.x * blockDim.x + threadIdx.x;
    if (e < EDGES) atomicAdd(&cnt[r0[e]], 1);
    else if (e < 2 * EDGES) atomicAdd(&cnt[NROWS + r1[e - EDGES]], 1);
}

__global__ void scan_block2_k(const int* __restrict__ cnt, int* __restrict__ incl,
                              int* __restrict__ bsums) {
    __shared__ int sm[1024];
    int gb = blockIdx.y * NROWS;
    int i = blockIdx.x * 1024 + threadIdx.x;
    int v = (i < NROWS) ? cnt[gb + i] : 0;
    sm[threadIdx.x] = v;
    __syncthreads();
#pragma unroll
    for (int o = 1; o < 1024; o <<= 1) {
        int t = (threadIdx.x >= o) ? sm[threadIdx.x - o] : 0;
        __syncthreads();
        sm[threadIdx.x] += t;
        __syncthreads();
    }
    if (i < NROWS) incl[gb + i] = sm[threadIdx.x];
    if (threadIdx.x == 1023) bsums[blockIdx.y * 64 + blockIdx.x] = sm[1023];
}

__global__ void scan_sums2_k(const int* __restrict__ bsums, int* __restrict__ bpre, int nb) {
    __shared__ int wsum;
    int gb = blockIdx.x * 64;
    int lane = threadIdx.x;
    int orig = (lane < nb) ? bsums[gb + lane] : 0;
    int v = orig;
#pragma unroll
    for (int o = 1; o < 32; o <<= 1) {
        int t = __shfl_up_sync(0xffffffffu, v, o);
        if ((lane & 31) >= o) v += t;
    }
    if (lane == 31) wsum = v;
    __syncthreads();
    int incl = v + ((lane >= 32) ? wsum : 0);
    if (lane < nb) bpre[gb + lane] = incl - orig;
}

__global__ void finalize2_k(const int* __restrict__ incl, const int* __restrict__ cnt,
                            const int* __restrict__ bpre, int* __restrict__ rowptr,
                            int* __restrict__ tmp) {
    int gidx = blockIdx.y;
    int i = blockIdx.x * blockDim.x + threadIdx.x;
    if (i < NROWS) {
        int ex = incl[gidx * NROWS + i] - cnt[gidx * NROWS + i] + bpre[gidx * 64 + (i >> 10)];
        rowptr[gidx * (NROWS + 1) + i] = ex;
        tmp[gidx * NROWS + i] = ex;
    }
    if (i == 0) rowptr[gidx * (NROWS + 1) + NROWS] = EDGES;
}

__global__ void scatter2_k(const int* __restrict__ e0, const int* __restrict__ e1,
                           int* __restrict__ tmp, int* __restrict__ cols) {
    int e = blockIdx.x * blockDim.x + threadIdx.x;
    if (e < EDGES) {
        int r = e0[e];
        int p = atomicAdd(&tmp[r], 1);
        cols[p] = e0[e + EDGES];
    } else if (e < 2 * EDGES) {
        int ee = e - EDGES;
        int r = e1[ee];
        int p = atomicAdd(&tmp[NROWS + r], 1);
        cols[EDGES + p] = e1[ee + EDGES];
    }
}

// ---------------- SpGAT aggregation (single view per launch) ----------------
template <int D>
__global__ void agg_k(const int* __restrict__ rp, const int* __restrict__ cl,
                      const float* __restrict__ f, const float* __restrict__ gg,
                      const float* __restrict__ h, float* __restrict__ out) {
    int row = (blockIdx.x * blockDim.x + threadIdx.x) >> 5;
    int lane = threadIdx.x & 31;
    if (row >= NROWS) return;
    int s = rp[row];
    int e = rp[row + 1];
    float fr = f[row];
    constexpr int V = D / 32;
    float acc[V];
#pragma unroll
    for (int j = 0; j < V; j++) acc[j] = 0.0f;
    float den = 0.0f;
    for (int p = s; p < e; p++) {
        int c = cl[p];
        float x = fr + gg[c];
        float lr = x > 0.0f ? x : ALPHA * x;
        float w = __expf(-lr);
        den += w;
        const float* hc = h + (size_t)c * D;
#pragma unroll
        for (int j = 0; j < V; j++) acc[j] = fmaf(w, hc[lane + j * 32], acc[j]);
    }
    float inv = 1.0f / (den + EPSV);
#pragma unroll
    for (int j = 0; j < V; j++) {
        float v = acc[j] * inv;
        v = v > 0.0f ? v : __expf(v) - 1.0f;  // ELU
        out[(size_t)row * D + lane + j * 32] = v;
    }
}

// ---------------- final fusion + classifier + log_softmax ----------------
__global__ void final_k(const float* __restrict__ twX, const float* __restrict__ tuX,
                        const int* __restrict__ g0, const int* __restrict__ g1,
                        const float* __restrict__ outW, const float* __restrict__ outB,
                        const float* __restrict__ att, float* __restrict__ out) {
    int b = (blockIdx.x * blockDim.x + threadIdx.x) >> 5;
    int lane = threadIdx.x & 31;
    if (b >= BATCH) return;
    float a0 = att[0] * (1.0f / NROWS);
    float a1 = att[1] * (1.0f / NROWS);
    float mx = fmaxf(a0, a1);
    float e0 = expf(a0 - mx), e1 = expf(a1 - mx);
    float inv = 1.0f / (e0 + e1);
    float w0 = e0 * inv, w1 = e1 * inv;
    int i0 = g0[b], i1 = g1[b];
    float l0 = 0.0f, l1 = 0.0f;
#pragma unroll
    for (int j = 0; j < JOINT / 32; j++) {
        int c = lane + j * 32;
        float fv = w0 * twX[(size_t)i0 * JOINT + c] + w1 * tuX[(size_t)i1 * JOINT + c];
        l0 = fmaf(fv, outW[c], l0);
        l1 = fmaf(fv, outW[JOINT + c], l1);
    }
#pragma unroll
    for (int o = 16; o; o >>= 1) {
        l0 += __shfl_xor_sync(0xffffffffu, l0, o);
        l1 += __shfl_xor_sync(0xffffffffu, l1, o);
    }
    if (lane == 0) {
        l0 += outB[0];
        l1 += outB[1];
        float m = fmaxf(l0, l1);
        float lse = m + logf(expf(l0 - m) + expf(l1 - m));
        out[b * 2 + 0] = l0 - lse;
        out[b * 2 + 1] = l1 - lse;
    }
}

// ---------------- host launcher ----------------
extern "C" void kernel_launch(void* const* d_in, const int* in_sizes, int n_in,
                              void* d_out, int out_size) {
    const float *word_emb, *user_emb, *tw_W1, *tw_a1, *tw_W2, *tw_a2;
    const float *tu_W1, *tu_a1, *tu_W2, *tu_a2, *weight_W, *weight_proj, *out_W, *out_b;
    const int *feat_idx, *tw_edges, *ut_edges, *tw_gidx, *ut_gidx;

    if (in_sizes[0] == NROWS * NFEAT) {
        word_emb    = (const float*)d_in[0];
        user_emb    = (const float*)d_in[1];
        tw_W1       = (const float*)d_in[2];
        tw_a1       = (const float*)d_in[3];
        tw_W2       = (const float*)d_in[4];
        tw_a2       = (const float*)d_in[5];
        tu_W1       = (const float*)d_in[6];
        tu_a1       = (const float*)d_in[7];
        tu_W2       = (const float*)d_in[8];
        tu_a2       = (const float*)d_in[9];
        weight_W    = (const float*)d_in[10];
        weight_proj = (const float*)d_in[11];
        out_W       = (const float*)d_in[12];
        out_b       = (const float*)d_in[13];
        feat_idx    = (const int*)d_in[14];
        tw_edges    = (const int*)d_in[15];
        ut_edges    = (const int*)d_in[16];
        tw_gidx     = (const int*)d_in[17];
        ut_gidx     = (const int*)d_in[18];
    } else {
        feat_idx    = (const int*)d_in[0];
        tw_edges    = (const int*)d_in[1];
        ut_edges    = (const int*)d_in[2];
        tw_gidx     = (const int*)d_in[3];
        ut_gidx     = (const int*)d_in[4];
        word_emb    = (const float*)d_in[5];
        user_emb    = (const float*)d_in[6];
        tw_W1       = (const float*)d_in[7];
        tw_a1       = (const float*)d_in[8];
        tw_W2       = (const float*)d_in[9];
        tw_a2       = (const float*)d_in[10];
        tu_W1       = (const float*)d_in[11];
        tu_a1       = (const float*)d_in[12];
        tu_W2       = (const float*)d_in[13];
        tu_a2       = (const float*)d_in[14];
        weight_W    = (const float*)d_in[15];
        weight_proj = (const float*)d_in[16];
        out_W       = (const float*)d_in[17];
        out_b       = (const float*)d_in[18];
    }

    float *Pw, *h1, *out1, *h2, *X, *fb, *gb, *att;
    int *cnt, *incl, *rowptr, *tmp, *cols, *bsums, *bpre;
    cudaGetSymbolAddress((void**)&Pw, g_Pw);
    cudaGetSymbolAddress((void**)&h1, g_h1);
    cudaGetSymbolAddress((void**)&out1, g_out1);
    cudaGetSymbolAddress((void**)&h2, g_h2);
    cudaGetSymbolAddress((void**)&X, g_X);
    cudaGetSymbolAddress((void**)&fb, g_f);
    cudaGetSymbolAddress((void**)&gb, g_g);
    cudaGetSymbolAddress((void**)&att, g_att);
    cudaGetSymbolAddress((void**)&cnt, g_cnt);
    cudaGetSymbolAddress((void**)&incl, g_incl);
    cudaGetSymbolAddress((void**)&rowptr, g_rowptr);
    cudaGetSymbolAddress((void**)&tmp, g_tmp);
    cudaGetSymbolAddress((void**)&cols, g_cols);
    cudaGetSymbolAddress((void**)&bsums, g_bsums);
    cudaGetSymbolAddress((void**)&bpre, g_bpre);

    float* h1_tw  = h1;
    float* h1_u   = h1 + (size_t)NROWS * HID;
    float* out1_u = out1 + (size_t)MPAD * HID;
    float* h2_u   = h2 + (size_t)MPAD * JOINT;
    float* X_u    = X + (size_t)MPAD * JOINT;

    const int WG = (NROWS * 32 + 255) / 256;
    const int GB = (NROWS + 127) / 128;        // 391
    const int NB = (NROWS + 1023) / 1024;      // 49
    const int NG = (NROWS + 255) / 256;
    const int E2G = (2 * EDGES + 255) / 256;

    static cudaStream_t s1 = nullptr, s2 = nullptr;
    static cudaEvent_t evFork = nullptr, evCSR = nullptr, evV1 = nullptr;
    if (s1 == nullptr) {
        cudaStreamCreateWithFlags(&s1, cudaStreamNonBlocking);
        cudaStreamCreateWithFlags(&s2, cudaStreamNonBlocking);
        cudaEventCreateWithFlags(&evFork, cudaEventDisableTiming);
        cudaEventCreateWithFlags(&evCSR, cudaEventDisableTiming);
        cudaEventCreateWithFlags(&evV1, cudaEventDisableTiming);
    }

    // ---- fork ----
    zero_att_k<<<1, 32>>>(att);
    cudaEventRecord(evFork, 0);
    cudaStreamWaitEvent(s1, evFork, 0);
    cudaStreamWaitEvent(s2, evFork, 0);

    // s1: CSR front
    zero_int_k<<<(2 * NROWS + 255) / 256, 256, 0, s1>>>(cnt, 2 * NROWS);
    count2_k<<<E2G, 256, 0, s1>>>(tw_edges, ut_edges, cnt);

    // main: view0 GEMM1 -> Pw  (ncu slot 3)
    gemm_k<128, 64, 8, 8, 8, 0, false><<<GB, 128>>>(
        word_emb, tw_W1, Pw, NROWS, NFEAT, nullptr, nullptr, nullptr, nullptr, nullptr);

    // s2: view1 GEMM1 -> h1_u (+ f/g layer1)
    gemm_k<128, 64, 8, 8, 8, 0, true><<<GB, 128, 0, s2>>>(
        user_emb, tu_W1, h1_u, NROWS, NFEAT, tu_a1, fb + MPAD, gb + MPAD, nullptr, nullptr);

    // s1: rest of CSR
    scan_block2_k<<<dim3(NB, 2), 1024, 0, s1>>>(cnt, incl, bsums);
    scan_sums2_k<<<2, 64, 0, s1>>>(bsums, bpre, NB);
    finalize2_k<<<dim3(NG, 2), 256, 0, s1>>>(incl, cnt, bpre, rowptr, tmp);
    scatter2_k<<<E2G, 256, 0, s1>>>(tw_edges, ut_edges, tmp, cols);
    cudaEventRecord(evCSR, s1);

    // main: tweet h1 = gather-mean (+ f/g layer1 view0)
    gather_mean_fg_k<<<WG, 256>>>(feat_idx, Pw, h1_tw, tw_a1, fb, gb);

    // ---- view0 chain on main ----
    cudaStreamWaitEvent(0, evCSR, 0);
    agg_k<HID><<<WG, 256>>>(rowptr, cols, fb, gb, h1_tw, out1);
    gemm_k<128, 128, 8, 8, 8, 0, true><<<GB, 256>>>(
        out1, tw_W2, h2, NROWS, HID, tw_a2, fb, gb, nullptr, nullptr);
    agg_k<JOINT><<<WG, 256>>>(rowptr, cols, fb, gb, h2, X);
    gemm_k<128, 128, 8, 8, 8, 1, false><<<GB, 256>>>(
        X, weight_W, nullptr, NROWS, JOINT, nullptr, nullptr, nullptr, weight_proj, att + 0);

    // ---- view1 chain on s2 ----
    cudaStreamWaitEvent(s2, evCSR, 0);
    agg_k<HID><<<WG, 256, 0, s2>>>(rowptr + (NROWS + 1), cols + EDGES,
                                   fb + MPAD, gb + MPAD, h1_u, out1_u);
    gemm_k<128, 128, 8, 8, 8, 0, true><<<GB, 256, 0, s2>>>(
        out1_u, tu_W2, h2_u, NROWS, HID, tu_a2, fb + MPAD, gb + MPAD, nullptr, nullptr);
    agg_k<JOINT><<<WG, 256, 0, s2>>>(rowptr + (NROWS + 1), cols + EDGES,
                                     fb + MPAD, gb + MPAD, h2_u, X_u);
    gemm_k<128, 128, 8, 8, 8, 1, false><<<GB, 256, 0, s2>>>(
        X_u, weight_W, nullptr, NROWS, JOINT, nullptr, nullptr, nullptr, weight_proj, att + 1);
    cudaEventRecord(evV1, s2);

    // ---- join + final ----
    cudaStreamWaitEvent(0, evV1, 0);
    final_k<<<(BATCH * 32 + 255) / 256, 256>>>(X, X_u, tw_gidx, ut_gidx,
                                               out_W, out_b, att, (float*)d_out);
}

// round 16
// speedup vs baseline: 1.3023x; 1.0376x over previous
#include <cuda_runtime.h>
#include <math.h>

// ---------------- problem constants ----------------
#define NROWS 50000
#define MPAD  50048
#define NFEAT 300
#define LWORDS 16
#define EDGES 800000
#define HID 64
#define JOINT 128
#define BATCH 4096
#define ALPHA 0.2f
#define EPSV 1e-16f

// ---------------- scratch ----------------
__device__ float g_Pw[(size_t)NROWS * HID];
__device__ float g_h1[2][(size_t)NROWS * HID];
__device__ float g_out1[2][(size_t)MPAD * HID];
__device__ float g_h2[2][(size_t)MPAD * JOINT];
__device__ float g_X[2][(size_t)MPAD * JOINT];
__device__ float g_f[2][MPAD];
__device__ float g_g[2][MPAD];
__device__ int   g_cnt[2][NROWS];
__device__ int   g_incl[2][NROWS];
__device__ int   g_rowptr[2][NROWS + 1];
__device__ int   g_tmp[2][NROWS];
__device__ int   g_cols[2][EDGES];
__device__ int   g_bsums[2][64];
__device__ int   g_bpre[2][64];
__device__ float g_att[2];

// ---------------- f32x2 helpers ----------------
__device__ __forceinline__ unsigned long long pack_dup(float a) {
    unsigned long long r;
    asm("mov.b64 %0,{%1,%1};" : "=l"(r) : "f"(a));
    return r;
}
__device__ __forceinline__ void fma_x2(unsigned long long& acc, unsigned long long a,
                                       unsigned long long b) {
    asm("fma.rn.f32x2 %0,%1,%2,%3;" : "=l"(acc) : "l"(a), "l"(b), "l"(acc));
}
__device__ __forceinline__ void unpack2(unsigned long long v, float& lo, float& hi) {
    asm("mov.b64 {%0,%1},%2;" : "=f"(lo), "=f"(hi) : "l"(v));
}
__device__ __forceinline__ float tanh_fast(float x) {
    float r;
    asm("tanh.approx.f32 %0,%1;" : "=f"(r) : "f"(x));
    return r;
}

// ---------------- small utility kernels ----------------
__global__ void zero_att_k(float* att) {
    if (threadIdx.x < 2) att[threadIdx.x] = 0.0f;
}

__global__ void zero_int_k(int* p, int n) {
    int i = blockIdx.x * blockDim.x + threadIdx.x;
    if (i < n) p[i] = 0;
}

// ---------------- GEMM (exact R9-winner core) ----------------
// k-major As, double-buffered smem, register prefetch, f32x2 packed FMA (pairs along M).
// MODE 0: store C (+ f/g epilogue if FUSE).  MODE 1: sum(tanh(C)*proj) -> atomicAdd(red).
template <int BM, int BN, int BK, int TM, int TN, int MODE, bool FUSE>
__global__ void __launch_bounds__((BM / TM) * (BN / TN))
gemm_k(const float* __restrict__ A, const float* __restrict__ Bm,
       float* __restrict__ C, int M, int K,
       const float* __restrict__ av, float* __restrict__ fo, float* __restrict__ go,
       const float* __restrict__ proj, float* __restrict__ red) {
    constexpr int TX = BN / TN;
    constexpr int TY = BM / TM;
    constexpr int NT = TX * TY;
    constexpr int KV = BK / 4;
    constexpr int NV = BN / 4;
    constexpr int AV4 = (BM * BK) / (4 * NT);
    constexpr int BV4 = (BK * BN) / (4 * NT);
    static_assert(AV4 * 4 * NT == BM * BK, "A tile divisible");
    static_assert(BV4 * 4 * NT == BK * BN, "B tile divisible");
    static_assert(TM % 4 == 0 && TN % 4 == 0, "frag vec");

    __shared__ __align__(16) float As[2][BK][BM + 4];
    __shared__ __align__(16) float Bs[2][BK][BN];

    int tid = threadIdx.x;
    int tx = tid % TX;
    int ty = tid / TX;
    int m0 = blockIdx.x * BM;
    int nk = (K + BK - 1) / BK;

    unsigned long long acc2[TM / 2][TN];
#pragma unroll
    for (int i = 0; i < TM / 2; i++)
#pragma unroll
        for (int j = 0; j < TN; j++) acc2[i][j] = 0ULL;

    float4 pa[AV4], pb[BV4];

    auto fetch = [&](int kb) {
        int k0 = kb * BK;
#pragma unroll
        for (int u = 0; u < AV4; u++) {
            int t = tid + u * NT;
            int m = t / KV, kq = t % KV;
            int gm = m0 + m, gk = k0 + kq * 4;
            float4 v = make_float4(0.f, 0.f, 0.f, 0.f);
            if (gm < M) {
                if (gk + 3 < K) {
                    v = *reinterpret_cast<const float4*>(&A[(size_t)gm * K + gk]);
                } else {
                    if (gk + 0 < K) v.x = A[(size_t)gm * K + gk + 0];
                    if (gk + 1 < K) v.y = A[(size_t)gm * K + gk + 1];
                    if (gk + 2 < K) v.z = A[(size_t)gm * K + gk + 2];
                    if (gk + 3 < K) v.w = A[(size_t)gm * K + gk + 3];
                }
            }
            pa[u] = v;
        }
#pragma unroll
        for (int u = 0; u < BV4; u++) {
            int t = tid + u * NT;
            int k = t / NV, nq = t % NV;
            int gk = k0 + k;
            float4 v = make_float4(0.f, 0.f, 0.f, 0.f);
            if (gk < K) v = *reinterpret_cast<const float4*>(&Bm[(size_t)gk * BN + nq * 4]);
            pb[u] = v;
        }
    };
    auto stage = [&](int buf) {
#pragma unroll
        for (int u = 0; u < AV4; u++) {
            int t = tid + u * NT;
            int m = t / KV, kq = t % KV;
            As[buf][kq * 4 + 0][m] = pa[u].x;
            As[buf][kq * 4 + 1][m] = pa[u].y;
            As[buf][kq * 4 + 2][m] = pa[u].z;
            As[buf][kq * 4 + 3][m] = pa[u].w;
        }
#pragma unroll
        for (int u = 0; u < BV4; u++) {
            int t = tid + u * NT;
            int k = t / NV, nq = t % NV;
            *reinterpret_cast<float4*>(&Bs[buf][k][nq * 4]) = pb[u];
        }
    };

    fetch(0);
    stage(0);
    __syncthreads();

    int buf = 0;
    for (int kb = 0; kb < nk; kb++) {
        if (kb + 1 < nk) fetch(kb + 1);
#pragma unroll
        for (int k = 0; k < BK; k++) {
            unsigned long long a2[TM / 2];
#pragma unroll
            for (int i = 0; i < TM; i += 4) {
                ulonglong2 u = *reinterpret_cast<const ulonglong2*>(&As[buf][k][ty * TM + i]);
                a2[i / 2] = u.x;
                a2[i / 2 + 1] = u.y;
            }
            unsigned long long bd[TN];
#pragma unroll
            for (int j = 0; j < TN; j += 4) {
                float4 b4 = *reinterpret_cast<const float4*>(&Bs[buf][k][tx * TN + j]);
                bd[j] = pack_dup(b4.x);
                bd[j + 1] = pack_dup(b4.y);
                bd[j + 2] = pack_dup(b4.z);
                bd[j + 3] = pack_dup(b4.w);
            }
#pragma unroll
            for (int i = 0; i < TM / 2; i++)
#pragma unroll
                for (int j = 0; j < TN; j++) fma_x2(acc2[i][j], a2[i], bd[j]);
        }
        if (kb + 1 < nk) stage(buf ^ 1);
        __syncthreads();
        buf ^= 1;
    }

    float val[TM][TN];
#pragma unroll
    for (int i = 0; i < TM / 2; i++)
#pragma unroll
        for (int j = 0; j < TN; j++) unpack2(acc2[i][j], val[2 * i][j], val[2 * i + 1][j]);

    if (MODE == 0) {
#pragma unroll
        for (int i = 0; i < TM; i++) {
            int m = m0 + ty * TM + i;
            if (m < M) {
#pragma unroll
                for (int j = 0; j < TN; j += 4) {
                    float4 v4 = make_float4(val[i][j], val[i][j + 1], val[i][j + 2], val[i][j + 3]);
                    *reinterpret_cast<float4*>(&C[(size_t)m * BN + tx * TN + j]) = v4;
                }
            }
        }
        if (FUSE) {
#pragma unroll
            for (int i = 0; i < TM; i++) {
                float sf = 0.0f, sg = 0.0f;
#pragma unroll
                for (int j = 0; j < TN; j++) {
                    int c = tx * TN + j;
                    sf = fmaf(val[i][j], av[c], sf);
                    sg = fmaf(val[i][j], av[BN + c], sg);
                }
#pragma unroll
                for (int o = TX / 2; o; o >>= 1) {
                    sf += __shfl_xor_sync(0xffffffffu, sf, o);
                    sg += __shfl_xor_sync(0xffffffffu, sg, o);
                }
                int m = m0 + ty * TM + i;
                if (tx == 0 && m < M) { fo[m] = sf; go[m] = sg; }
            }
        }
    } else {
        // OOB rows are zero-filled -> tanh(0)=0 contributes nothing
        float s = 0.0f;
#pragma unroll
        for (int j = 0; j < TN; j++) {
            float pj = proj[tx * TN + j];
#pragma unroll
            for (int i = 0; i < TM; i++) s = fmaf(tanh_fast(val[i][j]), pj, s);
        }
#pragma unroll
        for (int o = 16; o; o >>= 1) s += __shfl_xor_sync(0xffffffffu, s, o);
        __shared__ float wred[NT / 32];
        if ((tid & 31) == 0) wred[tid >> 5] = s;
        __syncthreads();
        if (tid == 0) {
            float tot = 0.0f;
            for (int w = 0; w < NT / 32; w++) tot += wred[w];
            atomicAdd(red, tot);
        }
    }
}

// ---------------- gather-mean + fused f/g (tweet layer 1), float2 per lane ----------------
__global__ void gather_mean_fg_k(const int* __restrict__ idx, const float* __restrict__ P,
                                 float* __restrict__ out, const float* __restrict__ a,
                                 float* __restrict__ f, float* __restrict__ g) {
    int row = (blockIdx.x * blockDim.x + threadIdx.x) >> 5;
    int lane = threadIdx.x & 31;
    if (row >= NROWS) return;
    int w = idx[row * LWORDS + (lane & 15)];
    float acc0 = 0.0f, acc1 = 0.0f;
#pragma unroll
    for (int l = 0; l < LWORDS; l++) {
        int wl = __shfl_sync(0xffffffffu, w, l);
        float2 hv = *reinterpret_cast<const float2*>(&P[(size_t)wl * HID + lane * 2]);
        acc0 += hv.x;
        acc1 += hv.y;
    }
    float h0 = acc0 * (1.0f / LWORDS);
    float h1 = acc1 * (1.0f / LWORDS);
    *reinterpret_cast<float2*>(&out[(size_t)row * HID + lane * 2]) = make_float2(h0, h1);
    int c0 = lane * 2, c1 = lane * 2 + 1;
    float sf = h0 * a[c0] + h1 * a[c1];
    float sg = h0 * a[HID + c0] + h1 * a[HID + c1];
#pragma unroll
    for (int o = 16; o; o >>= 1) {
        sf += __shfl_xor_sync(0xffffffffu, sf, o);
        sg += __shfl_xor_sync(0xffffffffu, sg, o);
    }
    if (lane == 0) { f[row] = sf; g[row] = sg; }
}

// ---------------- CSR build (both graphs per launch) ----------------
__global__ void count2_k(const int* __restrict__ r0, const int* __restrict__ r1,
                         int* __restrict__ cnt) {
    int e = blockIdx.x * blockDim.x + threadIdx.x;
    if (e < EDGES) atomicAdd(&cnt[r0[e]], 1);
    else if (e < 2 * EDGES) atomicAdd(&cnt[NROWS + r1[e - EDGES]], 1);
}

__global__ void scan_block2_k(const int* __restrict__ cnt, int* __restrict__ incl,
                              int* __restrict__ bsums) {
    __shared__ int sm[1024];
    int gb = blockIdx.y * NROWS;
    int i = blockIdx.x * 1024 + threadIdx.x;
    int v = (i < NROWS) ? cnt[gb + i] : 0;
    sm[threadIdx.x] = v;
    __syncthreads();
#pragma unroll
    for (int o = 1; o < 1024; o <<= 1) {
        int t = (threadIdx.x >= o) ? sm[threadIdx.x - o] : 0;
        __syncthreads();
        sm[threadIdx.x] += t;
        __syncthreads();
    }
    if (i < NROWS) incl[gb + i] = sm[threadIdx.x];
    if (threadIdx.x == 1023) bsums[blockIdx.y * 64 + blockIdx.x] = sm[1023];
}

__global__ void scan_sums2_k(const int* __restrict__ bsums, int* __restrict__ bpre, int nb) {
    __shared__ int wsum;
    int gb = blockIdx.x * 64;
    int lane = threadIdx.x;
    int orig = (lane < nb) ? bsums[gb + lane] : 0;
    int v = orig;
#pragma unroll
    for (int o = 1; o < 32; o <<= 1) {
        int t = __shfl_up_sync(0xffffffffu, v, o);
        if ((lane & 31) >= o) v += t;
    }
    if (lane == 31) wsum = v;
    __syncthreads();
    int incl = v + ((lane >= 32) ? wsum : 0);
    if (lane < nb) bpre[gb + lane] = incl - orig;
}

__global__ void finalize2_k(const int* __restrict__ incl, const int* __restrict__ cnt,
                            const int* __restrict__ bpre, int* __restrict__ rowptr,
                            int* __restrict__ tmp) {
    int gidx = blockIdx.y;
    int i = blockIdx.x * blockDim.x + threadIdx.x;
    if (i < NROWS) {
        int ex = incl[gidx * NROWS + i] - cnt[gidx * NROWS + i] + bpre[gidx * 64 + (i >> 10)];
        rowptr[gidx * (NROWS + 1) + i] = ex;
        tmp[gidx * NROWS + i] = ex;
    }
    if (i == 0) rowptr[gidx * (NROWS + 1) + NROWS] = EDGES;
}

__global__ void scatter2_k(const int* __restrict__ e0, const int* __restrict__ e1,
                           int* __restrict__ tmp, int* __restrict__ cols) {
    int e = blockIdx.x * blockDim.x + threadIdx.x;
    if (e < EDGES) {
        int r = e0[e];
        int p = atomicAdd(&tmp[r], 1);
        cols[p] = e0[e + EDGES];
    } else if (e < 2 * EDGES) {
        int ee = e - EDGES;
        int r = e1[ee];
        int p = atomicAdd(&tmp[NROWS + r], 1);
        cols[EDGES + p] = e1[ee + EDGES];
    }
}

// ---------------- SpGAT aggregation, vectorized (contiguous V floats per lane) ----------------
template <int D>
__global__ void agg_k(const int* __restrict__ rp, const int* __restrict__ cl,
                      const float* __restrict__ f, const float* __restrict__ gg,
                      const float* __restrict__ h, float* __restrict__ out) {
    int row = (blockIdx.x * blockDim.x + threadIdx.x) >> 5;
    int lane = threadIdx.x & 31;
    if (row >= NROWS) return;
    int s = rp[row];
    int e = rp[row + 1];
    float fr = f[row];
    constexpr int V = D / 32;  // 2 or 4 floats per lane, contiguous

    float acc[V];
#pragma unroll
    for (int j = 0; j < V; j++) acc[j] = 0.0f;
    float den = 0.0f;

#pragma unroll 2
    for (int p = s; p < e; p++) {
        int c = cl[p];
        float x = fr + gg[c];
        float lr = x > 0.0f ? x : ALPHA * x;
        float w = __expf(-lr);
        den += w;
        const float* hc = h + (size_t)c * D + lane * V;
        if (V == 4) {
            float4 hv = *reinterpret_cast<const float4*>(hc);
            acc[0] = fmaf(w, hv.x, acc[0]);
            acc[1] = fmaf(w, hv.y, acc[1]);
            acc[2] = fmaf(w, hv.z, acc[2]);
            acc[3] = fmaf(w, hv.w, acc[3]);
        } else {
            float2 hv = *reinterpret_cast<const float2*>(hc);
            acc[0] = fmaf(w, hv.x, acc[0]);
            acc[1] = fmaf(w, hv.y, acc[1]);
        }
    }
    float inv = 1.0f / (den + EPSV);
#pragma unroll
    for (int j = 0; j < V; j++) {
        float v = acc[j] * inv;
        acc[j] = v > 0.0f ? v : __expf(v) - 1.0f;  // ELU
    }
    float* op = out + (size_t)row * D + lane * V;
    if (V == 4) {
        *reinterpret_cast<float4*>(op) = make_float4(acc[0], acc[1], acc[2], acc[3]);
    } else {
        *reinterpret_cast<float2*>(op) = make_float2(acc[0], acc[1]);
    }
}

// ---------------- final fusion + classifier + log_softmax ----------------
__global__ void final_k(const float* __restrict__ twX, const float* __restrict__ tuX,
                        const int* __restrict__ g0, const int* __restrict__ g1,
                        const float* __restrict__ outW, const float* __restrict__ outB,
                        const float* __restrict__ att, float* __restrict__ out) {
    int b = (blockIdx.x * blockDim.x + threadIdx.x) >> 5;
    int lane = threadIdx.x & 31;
    if (b >= BATCH) return;
    float a0 = att[0] * (1.0f / NROWS);
    float a1 = att[1] * (1.0f / NROWS);
    float mx = fmaxf(a0, a1);
    float e0 = expf(a0 - mx), e1 = expf(a1 - mx);
    float inv = 1.0f / (e0 + e1);
    float w0 = e0 * inv, w1 = e1 * inv;
    int i0 = g0[b], i1 = g1[b];
    float l0 = 0.0f, l1 = 0.0f;
#pragma unroll
    for (int j = 0; j < JOINT / 32; j++) {
        int c = lane + j * 32;
        float fv = w0 * twX[(size_t)i0 * JOINT + c] + w1 * tuX[(size_t)i1 * JOINT + c];
        l0 = fmaf(fv, outW[c], l0);
        l1 = fmaf(fv, outW[JOINT + c], l1);
    }
#pragma unroll
    for (int o = 16; o; o >>= 1) {
        l0 += __shfl_xor_sync(0xffffffffu, l0, o);
        l1 += __shfl_xor_sync(0xffffffffu, l1, o);
    }
    if (lane == 0) {
        l0 += outB[0];
        l1 += outB[1];
        float m = fmaxf(l0, l1);
        float lse = m + logf(expf(l0 - m) + expf(l1 - m));
        out[b * 2 + 0] = l0 - lse;
        out[b * 2 + 1] = l1 - lse;
    }
}

// ---------------- host launcher ----------------
extern "C" void kernel_launch(void* const* d_in, const int* in_sizes, int n_in,
                              void* d_out, int out_size) {
    const float *word_emb, *user_emb, *tw_W1, *tw_a1, *tw_W2, *tw_a2;
    const float *tu_W1, *tu_a1, *tu_W2, *tu_a2, *weight_W, *weight_proj, *out_W, *out_b;
    const int *feat_idx, *tw_edges, *ut_edges, *tw_gidx, *ut_gidx;

    if (in_sizes[0] == NROWS * NFEAT) {
        word_emb    = (const float*)d_in[0];
        user_emb    = (const float*)d_in[1];
        tw_W1       = (const float*)d_in[2];
        tw_a1       = (const float*)d_in[3];
        tw_W2       = (const float*)d_in[4];
        tw_a2       = (const float*)d_in[5];
        tu_W1       = (const float*)d_in[6];
        tu_a1       = (const float*)d_in[7];
        tu_W2       = (const float*)d_in[8];
        tu_a2       = (const float*)d_in[9];
        weight_W    = (const float*)d_in[10];
        weight_proj = (const float*)d_in[11];
        out_W       = (const float*)d_in[12];
        out_b       = (const float*)d_in[13];
        feat_idx    = (const int*)d_in[14];
        tw_edges    = (const int*)d_in[15];
        ut_edges    = (const int*)d_in[16];
        tw_gidx     = (const int*)d_in[17];
        ut_gidx     = (const int*)d_in[18];
    } else {
        feat_idx    = (const int*)d_in[0];
        tw_edges    = (const int*)d_in[1];
        ut_edges    = (const int*)d_in[2];
        tw_gidx     = (const int*)d_in[3];
        ut_gidx     = (const int*)d_in[4];
        word_emb    = (const float*)d_in[5];
        user_emb    = (const float*)d_in[6];
        tw_W1       = (const float*)d_in[7];
        tw_a1       = (const float*)d_in[8];
        tw_W2       = (const float*)d_in[9];
        tw_a2       = (const float*)d_in[10];
        tu_W1       = (const float*)d_in[11];
        tu_a1       = (const float*)d_in[12];
        tu_W2       = (const float*)d_in[13];
        tu_a2       = (const float*)d_in[14];
        weight_W    = (const float*)d_in[15];
        weight_proj = (const float*)d_in[16];
        out_W       = (const float*)d_in[17];
        out_b       = (const float*)d_in[18];
    }

    float *Pw, *h1, *out1, *h2, *X, *fb, *gb, *att;
    int *cnt, *incl, *rowptr, *tmp, *cols, *bsums, *bpre;
    cudaGetSymbolAddress((void**)&Pw, g_Pw);
    cudaGetSymbolAddress((void**)&h1, g_h1);
    cudaGetSymbolAddress((void**)&out1, g_out1);
    cudaGetSymbolAddress((void**)&h2, g_h2);
    cudaGetSymbolAddress((void**)&X, g_X);
    cudaGetSymbolAddress((void**)&fb, g_f);
    cudaGetSymbolAddress((void**)&gb, g_g);
    cudaGetSymbolAddress((void**)&att, g_att);
    cudaGetSymbolAddress((void**)&cnt, g_cnt);
    cudaGetSymbolAddress((void**)&incl, g_incl);
    cudaGetSymbolAddress((void**)&rowptr, g_rowptr);
    cudaGetSymbolAddress((void**)&tmp, g_tmp);
    cudaGetSymbolAddress((void**)&cols, g_cols);
    cudaGetSymbolAddress((void**)&bsums, g_bsums);
    cudaGetSymbolAddress((void**)&bpre, g_bpre);

    float* h1_tw  = h1;
    float* h1_u   = h1 + (size_t)NROWS * HID;
    float* out1_u = out1 + (size_t)MPAD * HID;
    float* h2_u   = h2 + (size_t)MPAD * JOINT;
    float* X_u    = X + (size_t)MPAD * JOINT;

    const int WG = (NROWS * 32 + 255) / 256;
    const int GB = (NROWS + 127) / 128;        // 391
    const int NB = (NROWS + 1023) / 1024;      // 49
    const int NG = (NROWS + 255) / 256;
    const int E2G = (2 * EDGES + 255) / 256;

    static cudaStream_t s1 = nullptr, s2 = nullptr;
    static cudaEvent_t evFork = nullptr, evCSR = nullptr, evV1 = nullptr;
    if (s1 == nullptr) {
        cudaStreamCreateWithFlags(&s1, cudaStreamNonBlocking);
        cudaStreamCreateWithFlags(&s2, cudaStreamNonBlocking);
        cudaEventCreateWithFlags(&evFork, cudaEventDisableTiming);
        cudaEventCreateWithFlags(&evCSR, cudaEventDisableTiming);
        cudaEventCreateWithFlags(&evV1, cudaEventDisableTiming);
    }

    // ---- fork ----
    zero_att_k<<<1, 32>>>(att);
    cudaEventRecord(evFork, 0);
    cudaStreamWaitEvent(s1, evFork, 0);
    cudaStreamWaitEvent(s2, evFork, 0);

    // s1: CSR front
    zero_int_k<<<(2 * NROWS + 255) / 256, 256, 0, s1>>>(cnt, 2 * NROWS);
    count2_k<<<E2G, 256, 0, s1>>>(tw_edges, ut_edges, cnt);

    // main: view0 GEMM1 -> Pw  (ncu slot 3)
    gemm_k<128, 64, 8, 8, 8, 0, false><<<GB, 128>>>(
        word_emb, tw_W1, Pw, NROWS, NFEAT, nullptr, nullptr, nullptr, nullptr, nullptr);

    // s2: view1 GEMM1 -> h1_u (+ f/g layer1)
    gemm_k<128, 64, 8, 8, 8, 0, true><<<GB, 128, 0, s2>>>(
        user_emb, tu_W1, h1_u, NROWS, NFEAT, tu_a1, fb + MPAD, gb + MPAD, nullptr, nullptr);

    // s1: rest of CSR
    scan_block2_k<<<dim3(NB, 2), 1024, 0, s1>>>(cnt, incl, bsums);
    scan_sums2_k<<<2, 64, 0, s1>>>(bsums, bpre, NB);
    finalize2_k<<<dim3(NG, 2), 256, 0, s1>>>(incl, cnt, bpre, rowptr, tmp);
    scatter2_k<<<E2G, 256, 0, s1>>>(tw_edges, ut_edges, tmp, cols);
    cudaEventRecord(evCSR, s1);

    // main: tweet h1 = gather-mean (+ f/g layer1 view0)
    gather_mean_fg_k<<<WG, 256>>>(feat_idx, Pw, h1_tw, tw_a1, fb, gb);

    // ---- view0 chain on main ----
    cudaStreamWaitEvent(0, evCSR, 0);
    agg_k<HID><<<WG, 256>>>(rowptr, cols, fb, gb, h1_tw, out1);
    gemm_k<128, 128, 8, 8, 8, 0, true><<<GB, 256>>>(
        out1, tw_W2, h2, NROWS, HID, tw_a2, fb, gb, nullptr, nullptr);
    agg_k<JOINT><<<WG, 256>>>(rowptr, cols, fb, gb, h2, X);
    gemm_k<128, 128, 8, 8, 8, 1, false><<<GB, 256>>>(
        X, weight_W, nullptr, NROWS, JOINT, nullptr, nullptr, nullptr, weight_proj, att + 0);

    // ---- view1 chain on s2 ----
    cudaStreamWaitEvent(s2, evCSR, 0);
    agg_k<HID><<<WG, 256, 0, s2>>>(rowptr + (NROWS + 1), cols + EDGES,
                                   fb + MPAD, gb + MPAD, h1_u, out1_u);
    gemm_k<128, 128, 8, 8, 8, 0, true><<<GB, 256, 0, s2>>>(
        out1_u, tu_W2, h2_u, NROWS, HID, tu_a2, fb + MPAD, gb + MPAD, nullptr, nullptr);
    agg_k<JOINT><<<WG, 256, 0, s2>>>(rowptr + (NROWS + 1), cols + EDGES,
                                     fb + MPAD, gb + MPAD, h2_u, X_u);
    gemm_k<128, 128, 8, 8, 8, 1, false><<<GB, 256, 0, s2>>>(
        X_u, weight_W, nullptr, NROWS, JOINT, nullptr, nullptr, nullptr, weight_proj, att + 1);
    cudaEventRecord(evV1, s2);

    // ---- join + final ----
    cudaStreamWaitEvent(0, evV1, 0);
    final_k<<<(BATCH * 32 + 255) / 256, 256>>>(X, X_u, tw_gidx, ut_gidx,
                                               out_W, out_b, att, (float*)d_out);
}